// round 15
// baseline (speedup 1.0000x reference)
#include <cuda_runtime.h>
#include <cuda_fp16.h>
#include <math.h>
#include <stdint.h>

#define B_   2
#define L_   2048
#define E_   1024
#define H_   16
#define DH_  64
#define HID_ 4096
#define BH_  (B_*H_)    /* 32   */
#define ML_  (B_*L_)    /* 4096 */
#define QKV_LD 3072
#define KSCALE 0.18033688011112043f   /* log2(e)/8 */

// ---------------- scratch (device globals; no allocation allowed) ----------------
__device__ __align__(128) __half g_Ehi[(size_t)BH_ * L_ * L_];   // [bh][j][i] = exp(S^T), fp16
__device__ __align__(128) float  g_den[(size_t)BH_ * L_];

__device__ __align__(128) __half g_Ahi [(size_t)ML_ * E_];       // z hi, later O
__device__ __align__(128) __half g_Bthi[(size_t)HID_ * E_];      // transposed weights [N,K]
__device__ __align__(128) __half g_QKVhi[(size_t)ML_ * QKV_LD]; // [ML][Q|K'|V] (K pre-scaled)
__device__ __align__(128) __half g_Uh  [(size_t)BH_ * L_ * DH_];
__device__ __align__(128) float  g_biasP[QKV_LD];

// ---------------- ptx helpers (sm_80-compatible PTX only) ----------------
__device__ __forceinline__ uint32_t smem_u32(const void* p) {
    uint32_t a;
    asm("{ .reg .u64 t; cvta.to.shared.u64 t, %1; cvt.u32.u64 %0, t; }" : "=r"(a) : "l"(p));
    return a;
}
__device__ __forceinline__ void cp16(uint32_t saddr, const void* g) {
    asm volatile("cp.async.cg.shared.global [%0], [%1], 16;" :: "r"(saddr), "l"(g));
}
#define CP_COMMIT() asm volatile("cp.async.commit_group;" ::: "memory")
#define CP_WAIT0()  asm volatile("cp.async.wait_group 0;" ::: "memory")
#define CP_WAIT1()  asm volatile("cp.async.wait_group 1;" ::: "memory")

__device__ __forceinline__ void ldsm_x4(uint32_t* r, uint32_t a) {
    asm volatile("ldmatrix.sync.aligned.m8n8.x4.shared.b16 {%0,%1,%2,%3}, [%4];"
        : "=r"(r[0]), "=r"(r[1]), "=r"(r[2]), "=r"(r[3]) : "r"(a));
}
__device__ __forceinline__ void ldsm_x4t(uint32_t* r, uint32_t a) {
    asm volatile("ldmatrix.sync.aligned.m8n8.x4.trans.shared.b16 {%0,%1,%2,%3}, [%4];"
        : "=r"(r[0]), "=r"(r[1]), "=r"(r[2]), "=r"(r[3]) : "r"(a));
}
__device__ __forceinline__ void mma_f16(float* d, const uint32_t* a, const uint32_t* b) {
    asm volatile("mma.sync.aligned.m16n8k16.row.col.f32.f16.f16.f32 "
        "{%0,%1,%2,%3}, {%4,%5,%6,%7}, {%8,%9}, {%0,%1,%2,%3};"
        : "+f"(d[0]), "+f"(d[1]), "+f"(d[2]), "+f"(d[3])
        : "r"(a[0]), "r"(a[1]), "r"(a[2]), "r"(a[3]), "r"(b[0]), "r"(b[1]));
}

__device__ __forceinline__ float gelu_exact(float v) {
    return 0.5f * v * (1.0f + erff(v * 0.7071067811865476f));
}

// ---------------- init: pack bias (bk pre-scaled), init out=b2, zero den ----------------
__global__ void __launch_bounds__(256) init_kernel(const float* __restrict__ bq,
                                                   const float* __restrict__ bk,
                                                   const float* __restrict__ bv,
                                                   const float* __restrict__ b2,
                                                   float* __restrict__ out)
{
    int i = blockIdx.x * 256 + threadIdx.x;
    if (i < 1024)      g_biasP[i] = bq[i];
    else if (i < 2048) g_biasP[i] = bk[i - 1024] * KSCALE;
    else if (i < 3072) g_biasP[i] = bv[i - 2048];
    if (i < ML_) out[i] = b2[0];
    if (i < BH_ * L_) g_den[i] = 0.0f;
}

// ---------------- conversion kernels ----------------
__global__ void __launch_bounds__(256) convert_hi(const float* __restrict__ in,
                                                  __half* __restrict__ hi)
{
    size_t i = (size_t)blockIdx.x * 1024 + threadIdx.x * 4;
    float4 v = *(const float4*)(in + i);
    ((__half2*)(hi + i))[0] = __floats2half2_rn(v.x, v.y);
    ((__half2*)(hi + i))[1] = __floats2half2_rn(v.z, v.w);
}

// Wq/Wk/Wv fp32 [K,N] -> packed Th[N,K] fp16 (Wk pre-scaled by KSCALE)
__global__ void __launch_bounds__(256) transpose_qkv(const float* __restrict__ Wq,
                                                     const float* __restrict__ Wk,
                                                     const float* __restrict__ Wv,
                                                     __half* __restrict__ Th)
{
    __shared__ float sm[32][33];
    const float* W = (blockIdx.z == 0) ? Wq : (blockIdx.z == 1) ? Wk : Wv;
    const float scale = (blockIdx.z == 1) ? KSCALE : 1.0f;
    __half* T = Th + (size_t)blockIdx.z * E_ * E_;
    const int n0 = blockIdx.x * 32, k0 = blockIdx.y * 32;
    const int tx = threadIdx.x & 31, ty = threadIdx.x >> 5;
    #pragma unroll
    for (int i = 0; i < 4; i++)
        sm[ty + i * 8][tx] = W[(size_t)(k0 + ty + i * 8) * E_ + n0 + tx];
    __syncthreads();
    #pragma unroll
    for (int i = 0; i < 4; i++) {
        float v = sm[tx][ty + i * 8] * scale;
        T[(size_t)(n0 + ty + i * 8) * E_ + k0 + tx] = __float2half_rn(v);
    }
}

// W[K,N] fp32 -> Th[N,K] fp16
__global__ void __launch_bounds__(256) transpose_hi(const float* __restrict__ W,
                                                    __half* __restrict__ Th,
                                                    int K, int N)
{
    __shared__ float sm[32][33];
    const int n0 = blockIdx.x * 32, k0 = blockIdx.y * 32;
    const int tx = threadIdx.x & 31, ty = threadIdx.x >> 5;
    #pragma unroll
    for (int i = 0; i < 4; i++)
        sm[ty + i * 8][tx] = W[(size_t)(k0 + ty + i * 8) * N + n0 + tx];
    __syncthreads();
    #pragma unroll
    for (int i = 0; i < 4; i++) {
        float v = sm[tx][ty + i * 8];
        Th[(size_t)(n0 + ty + i * 8) * K + k0 + tx] = __float2half_rn(v);
    }
}

// ---------------- mma.sync fp16 GEMM (1-term: C = Ah @ Bh^T) ----------------
// MODE 0: C = A@B^T + bias -> fp16 out (QKV projection)
// MODE 1: per-head E = exp2(A@B^T) -> fp16 out + atomic denom (QK, K pre-scaled)
// MODE 2: y = gelu(A@B^T + bias); atomicAdd(out[row], y . W2)  (MLP + final)
// __launch_bounds__(256, 1): allow ptxas up to 255 regs for fragment pipelining
#define G_STAGE 32768   /* Ah 16K | Bh 16K */
#define G_SMEM  (2*G_STAGE + 1024)

template<int MODE>
__global__ void __launch_bounds__(256, 1) gemm_mma(
    const __half* __restrict__ Ahi,
    const __half* __restrict__ Bhi,
    const float* __restrict__ bias, const float* __restrict__ xw,
    __half* __restrict__ Chi,
    float* __restrict__ aux,
    int lda, int ldb, int ldc, int K)
{
    extern __shared__ char smraw[];
    uint32_t smb = smem_u32(smraw);
    smb = (smb + 1023u) & ~1023u;

    const int tid = threadIdx.x, lane = tid & 31, warp = tid >> 5;
    const int wm = warp & 1, wn = warp >> 1;

    size_t aOff = 0, bOff = 0, eOff = 0;
    int bh = 0, bb = 0;
    if (MODE == 1) {
        bh = blockIdx.z; bb = bh >> 4;
        const int h = bh & 15;
        aOff = (size_t)bb * L_ * QKV_LD + 1024 + h * DH_;   // K' vectors
        bOff = (size_t)bb * L_ * QKV_LD + h * DH_;          // Q vectors
        eOff = (size_t)bh * L_ * L_;
    }
    const int m0g = blockIdx.y * 128, n0g = blockIdx.x * 128;

    const char* gA = (const char*)(Ahi + aOff + (size_t)m0g * lda);
    const char* gB = (const char*)(Bhi + bOff + (size_t)n0g * ldb);

    const int nCh = K >> 6;
    float acc[4][4][4] = {};

    auto loadStage = [&](int st, int k0) {
        #pragma unroll
        for (int arr = 0; arr < 2; arr++) {
            const char* base = (arr == 0) ? gA : gB;
            const int ld2 = ((arr == 0) ? lda : ldb) * 2;
            const uint32_t sb = smb + st * G_STAGE + arr * 16384;
            #pragma unroll
            for (int q = 0; q < 4; q++) {
                int id = tid + q * 256;
                int row = id >> 3, c16 = (id & 7) << 4;
                uint32_t sa = sb + row * 128 + (c16 ^ ((row & 7) << 4));
                cp16(sa, base + (size_t)row * ld2 + k0 * 2 + c16);
            }
        }
    };

    loadStage(0, 0);
    CP_COMMIT();

    for (int c = 0; c < nCh; c++) {
        const int st = c & 1;
        if (c + 1 < nCh) { loadStage(st ^ 1, (c + 1) << 6); CP_COMMIT(); CP_WAIT1(); }
        else             { CP_WAIT0(); }
        __syncthreads();

        const uint32_t sA = smb + st * G_STAGE;
        const uint32_t sB = sA + 16384;
        #pragma unroll
        for (int s = 0; s < 4; s++) {
            const int kb = s * 32;
            uint32_t aH[4][4], bH[4][2];
            const int lr = lane & 15, lc = lane >> 4;
            #pragma unroll
            for (int mt = 0; mt < 4; mt++) {
                int r = wm * 64 + mt * 16 + lr;
                int cb = kb + lc * 16;
                uint32_t ad = sA + r * 128 + (cb ^ ((r & 7) << 4));
                ldsm_x4(aH[mt], ad);
            }
            // B: two x4 loads, each covering a pair of n-tiles
            #pragma unroll
            for (int np = 0; np < 2; np++) {
                int r = wn * 32 + np * 16 + ((lane >> 4) << 3) + (lane & 7);
                int cb = kb + (((lane >> 3) & 1) << 4);
                uint32_t bd = sB + r * 128 + (cb ^ ((r & 7) << 4));
                uint32_t t[4];
                ldsm_x4(t, bd);
                bH[np * 2 + 0][0] = t[0]; bH[np * 2 + 0][1] = t[1];
                bH[np * 2 + 1][0] = t[2]; bH[np * 2 + 1][1] = t[3];
            }
            #pragma unroll
            for (int mt = 0; mt < 4; mt++)
                #pragma unroll
                for (int nt = 0; nt < 4; nt++)
                    mma_f16(acc[mt][nt], aH[mt], bH[nt]);
        }
        __syncthreads();
    }

    // ---- epilogues ----
    if (MODE == 0) {
        #pragma unroll
        for (int mt = 0; mt < 4; mt++) {
            #pragma unroll
            for (int nt = 0; nt < 4; nt++) {
                const int row = m0g + wm * 64 + mt * 16 + (lane >> 2);
                const int col = n0g + wn * 32 + nt * 8 + 2 * (lane & 3);
                float b0 = __ldg(bias + col), b1 = __ldg(bias + col + 1);
                *(__half2*)(Chi + (size_t)row * ldc + col) = __halves2half2(
                    __float2half_rn(acc[mt][nt][0] + b0),
                    __float2half_rn(acc[mt][nt][1] + b1));
                *(__half2*)(Chi + (size_t)(row + 8) * ldc + col) = __halves2half2(
                    __float2half_rn(acc[mt][nt][2] + b0),
                    __float2half_rn(acc[mt][nt][3] + b1));
            }
        }
    } else if (MODE == 1) {
        const float* xb = xw + bb * L_;
        float xc[4][2];
        #pragma unroll
        for (int nt = 0; nt < 4; nt++) {
            int col = n0g + wn * 32 + nt * 8 + 2 * (lane & 3);
            xc[nt][0] = __ldg(xb + col);
            xc[nt][1] = __ldg(xb + col + 1);
        }
        #pragma unroll
        for (int mt = 0; mt < 4; mt++) {
            const int rg = m0g + wm * 64 + mt * 16 + (lane >> 2);
            float p0 = 0.0f, p8 = 0.0f;
            #pragma unroll
            for (int nt = 0; nt < 4; nt++) {
                const int col = n0g + wn * 32 + nt * 8 + 2 * (lane & 3);
                float e0 = exp2f(acc[mt][nt][0]);
                float e1 = exp2f(acc[mt][nt][1]);
                float e2 = exp2f(acc[mt][nt][2]);
                float e3 = exp2f(acc[mt][nt][3]);
                *(__half2*)(Chi + eOff + (size_t)rg * ldc + col) =
                    __halves2half2(__float2half_rn(e0), __float2half_rn(e1));
                *(__half2*)(Chi + eOff + (size_t)(rg + 8) * ldc + col) =
                    __halves2half2(__float2half_rn(e2), __float2half_rn(e3));
                p0 += xc[nt][0] * e0 + xc[nt][1] * e1;
                p8 += xc[nt][0] * e2 + xc[nt][1] * e3;
            }
            p0 += __shfl_xor_sync(0xffffffffu, p0, 1);
            p0 += __shfl_xor_sync(0xffffffffu, p0, 2);
            p8 += __shfl_xor_sync(0xffffffffu, p8, 1);
            p8 += __shfl_xor_sync(0xffffffffu, p8, 2);
            if ((lane & 3) == 0) {
                atomicAdd(aux + (size_t)bh * L_ + rg,     p0);
                atomicAdd(aux + (size_t)bh * L_ + rg + 8, p8);
            }
        }
    } else {  // MODE == 2
        #pragma unroll
        for (int mt = 0; mt < 4; mt++) {
            const int row = m0g + wm * 64 + mt * 16 + (lane >> 2);
            float p0 = 0.0f, p8 = 0.0f;
            #pragma unroll
            for (int nt = 0; nt < 4; nt++) {
                const int col = n0g + wn * 32 + nt * 8 + 2 * (lane & 3);
                float b0 = __ldg(bias + col), b1 = __ldg(bias + col + 1);
                float w0 = __ldg(xw + col),  w1 = __ldg(xw + col + 1);
                float v0 = gelu_exact(acc[mt][nt][0] + b0);
                float v1 = gelu_exact(acc[mt][nt][1] + b1);
                float v2 = gelu_exact(acc[mt][nt][2] + b0);
                float v3 = gelu_exact(acc[mt][nt][3] + b1);
                p0 += v0 * w0 + v1 * w1;
                p8 += v2 * w0 + v3 * w1;
            }
            p0 += __shfl_xor_sync(0xffffffffu, p0, 1);
            p0 += __shfl_xor_sync(0xffffffffu, p0, 2);
            p8 += __shfl_xor_sync(0xffffffffu, p8, 1);
            p8 += __shfl_xor_sync(0xffffffffu, p8, 2);
            if ((lane & 3) == 0) {
                atomicAdd(aux + row,     p0);
                atomicAdd(aux + row + 8, p8);
            }
        }
    }
}

// ---------------- U kernel: U[bh][j][d] = x_j * V[b,j,h,d] / den[bh][j] (fp16) ----------------
__global__ void __launch_bounds__(256) u_kernel(const float* __restrict__ x)
{
    int gid = blockIdx.x * 256 + threadIdx.x;
    int d = gid & 63;
    int row = gid >> 6;                          // bh*L + j
    int bh = row >> 11, j = row & (L_ - 1);
    int b = bh >> 4, h = bh & 15;
    float den = g_den[row];
    size_t vo = ((size_t)b * L_ + j) * QKV_LD + 2048 + h * DH_ + d;
    float v = __half2float(g_QKVhi[vo]);
    float u = __ldg(x + b * L_ + j) * v / den;
    g_Uh[(size_t)row * DH_ + d] = __float2half_rn(u);
}

// ---------------- attention output: O[i,d] = x_i * sum_j E[j,i]*U[j,d] ----------------
#define AT_STAGE 24576  /* Eh 16K | Uh 8K */
#define AT_SMEM  (2*AT_STAGE + 1024)

__global__ void __launch_bounds__(256) attn_mma(const float* __restrict__ x)
{
    extern __shared__ char smraw[];
    uint32_t smb = smem_u32(smraw);
    smb = (smb + 1023u) & ~1023u;

    const int tid = threadIdx.x, lane = tid & 31, warp = tid >> 5;
    const int wi = warp & 3, wd = warp >> 2;     // warp tile: 32 i x 32 d
    const int bh = blockIdx.y, b = bh >> 4, h = bh & 15;
    const int i0 = blockIdx.x * 128;

    const char* Ehb = (const char*)(g_Ehi + (size_t)bh * L_ * L_);
    const char* Uhb = (const char*)(g_Uh + (size_t)bh * L_ * DH_);

    float acc[2][4][4] = {};

    auto loadStage = [&](int st, int j0) {
        const uint32_t sb = smb + st * AT_STAGE;
        #pragma unroll
        for (int q = 0; q < 4; q++) {
            int id = tid + q * 256;
            int row = id >> 4, c16 = (id & 15) << 4;
            uint32_t soff = row * 256 + (c16 ^ ((row & 7) << 4));
            size_t go = (size_t)(j0 + row) * (L_ * 2) + (size_t)i0 * 2 + c16;
            cp16(sb + soff, Ehb + go);
        }
        #pragma unroll
        for (int q = 0; q < 2; q++) {
            int id = tid + q * 256;
            int row = id >> 3, c16 = (id & 7) << 4;
            uint32_t uoff = row * 128 + (c16 ^ ((row & 7) << 4));
            cp16(sb + 16384 + uoff, Uhb + (size_t)(j0 + row) * 128 + c16);
        }
    };

    loadStage(0, 0);
    CP_COMMIT();

    for (int c = 0; c < L_ / 64; c++) {
        const int st = c & 1;
        if (c + 1 < L_ / 64) { loadStage(st ^ 1, (c + 1) * 64); CP_COMMIT(); CP_WAIT1(); }
        else                 { CP_WAIT0(); }
        __syncthreads();

        const uint32_t sb = smb + st * AT_STAGE;
        #pragma unroll
        for (int s = 0; s < 4; s++) {
            const int k0 = s * 16;
            uint32_t eH[2][4], uH[4][2];
            {
                const int r = k0 + (lane & 7) + ((lane >> 4) << 3);
                const int cbl = (((lane >> 3) & 1) << 4);
                #pragma unroll
                for (int mt = 0; mt < 2; mt++) {
                    int cb = (wi * 32 + mt * 16) * 2 + cbl;
                    uint32_t ad = sb + r * 256 + (cb ^ ((r & 7) << 4));
                    ldsm_x4t(eH[mt], ad);
                }
            }
            // U: two x4t loads, each covering a pair of n(d)-tiles
            {
                const int r = k0 + (lane & 7) + (((lane >> 3) & 1) << 3);
                #pragma unroll
                for (int np = 0; np < 2; np++) {
                    int cb = (wd * 32 + np * 16 + ((lane >> 4) << 3)) * 2;
                    uint32_t ud = sb + 16384 + r * 128 + (cb ^ ((r & 7) << 4));
                    uint32_t t[4];
                    ldsm_x4t(t, ud);
                    uH[np * 2 + 0][0] = t[0]; uH[np * 2 + 0][1] = t[1];
                    uH[np * 2 + 1][0] = t[2]; uH[np * 2 + 1][1] = t[3];
                }
            }
            #pragma unroll
            for (int mt = 0; mt < 2; mt++)
                #pragma unroll
                for (int nt = 0; nt < 4; nt++)
                    mma_f16(acc[mt][nt], eH[mt], uH[nt]);
        }
        __syncthreads();
    }

    // epilogue: O fp16 hi-only into g_Ahi [ML][E]
    #pragma unroll
    for (int mt = 0; mt < 2; mt++) {
        #pragma unroll
        for (int nt = 0; nt < 4; nt++) {
            const int row = i0 + wi * 32 + mt * 16 + (lane >> 2);
            const int col = h * DH_ + wd * 32 + nt * 8 + 2 * (lane & 3);
            float x0 = __ldg(x + b * L_ + row);
            float x1 = __ldg(x + b * L_ + row + 8);
            size_t r0 = ((size_t)b * L_ + row) * E_ + col;
            size_t r8 = ((size_t)b * L_ + row + 8) * E_ + col;
            *(__half2*)(g_Ahi + r0) = __halves2half2(
                __float2half_rn(acc[mt][nt][0] * x0),
                __float2half_rn(acc[mt][nt][1] * x0));
            *(__half2*)(g_Ahi + r8) = __halves2half2(
                __float2half_rn(acc[mt][nt][2] * x1),
                __float2half_rn(acc[mt][nt][3] * x1));
        }
    }
}

// ---------------- launch ----------------
extern "C" void kernel_launch(void* const* d_in, const int* in_sizes, int n_in,
                              void* d_out, int out_size)
{
    (void)in_sizes; (void)n_in; (void)out_size;
    const float* x  = (const float*)d_in[0];
    const float* z  = (const float*)d_in[1];
    const float* Wq = (const float*)d_in[2];
    const float* bq = (const float*)d_in[3];
    const float* Wk = (const float*)d_in[4];
    const float* bk = (const float*)d_in[5];
    const float* Wv = (const float*)d_in[6];
    const float* bv = (const float*)d_in[7];
    const float* W1 = (const float*)d_in[8];
    const float* b1 = (const float*)d_in[9];
    const float* W2 = (const float*)d_in[10];
    const float* b2 = (const float*)d_in[11];
    float* out = (float*)d_out;

    __half *pAhi, *pBhi, *pQKVhi, *pEhi;
    float *pDen, *pBiasP;
    cudaGetSymbolAddress((void**)&pAhi, g_Ahi);
    cudaGetSymbolAddress((void**)&pBhi, g_Bthi);
    cudaGetSymbolAddress((void**)&pQKVhi, g_QKVhi);
    cudaGetSymbolAddress((void**)&pEhi, g_Ehi);
    cudaGetSymbolAddress((void**)&pDen, g_den);
    cudaGetSymbolAddress((void**)&pBiasP, g_biasP);

    cudaFuncSetAttribute(gemm_mma<0>, cudaFuncAttributeMaxDynamicSharedMemorySize, G_SMEM);
    cudaFuncSetAttribute(gemm_mma<1>, cudaFuncAttributeMaxDynamicSharedMemorySize, G_SMEM);
    cudaFuncSetAttribute(gemm_mma<2>, cudaFuncAttributeMaxDynamicSharedMemorySize, G_SMEM);
    cudaFuncSetAttribute(attn_mma, cudaFuncAttributeMaxDynamicSharedMemorySize, AT_SMEM);

    const size_t nZ = (size_t)ML_ * E_;

    // init: packed bias (bk pre-scaled), out = b2, den = 0
    init_kernel<<<256, 256>>>(bq, bk, bv, b2, out);

    // convert z -> fp16 hi
    convert_hi<<<nZ / 1024, 256>>>(z, pAhi);

    // pack transposed QKV weights (fused; Wk pre-scaled by log2e/8)
    transpose_qkv<<<dim3(E_ / 32, E_ / 32, 3), 256>>>(Wq, Wk, Wv, pBhi);

    // fused QKV projection -> fp16 [ML][3072]  (1-term, hi out)
    gemm_mma<0><<<dim3(QKV_LD / 128, ML_ / 128), 256, G_SMEM>>>(
        pAhi, pBhi, pBiasP, nullptr, pQKVhi, nullptr,
        E_, E_, QKV_LD, E_);

    // QK: E = exp2(K'_j . Q_i) fp16 + atomic denom  (1-term)
    gemm_mma<1><<<dim3(L_ / 128, L_ / 128, BH_), 256, G_SMEM>>>(
        pQKVhi, pQKVhi, nullptr, x, pEhi, pDen,
        QKV_LD, QKV_LD, L_, DH_);

    // U = x_j * V / den, fp16
    u_kernel<<<(BH_ * L_ * DH_) / 256, 256>>>(x);

    // attention output -> O fp16 (hi only, into g_Ahi)  (1-term)
    attn_mma<<<dim3(L_ / 128, BH_), 256, AT_SMEM>>>(x);

    // W1 transpose (hi only)
    transpose_hi<<<dim3(HID_ / 32, E_ / 32), 256>>>(W1, pBhi, E_, HID_);

    // MLP1 + fused W2 reduction -> out (atomic, 1-term)
    gemm_mma<2><<<dim3(HID_ / 128, ML_ / 128), 256, G_SMEM>>>(
        pAhi, pBhi, b1, W2, nullptr, out,
        E_, E_, 0, E_);
}

// round 16
// speedup vs baseline: 1.2797x; 1.2797x over previous
#include <cuda_runtime.h>
#include <cuda_fp16.h>
#include <math.h>
#include <stdint.h>

#define B_   2
#define L_   2048
#define E_   1024
#define H_   16
#define DH_  64
#define HID_ 4096
#define BH_  (B_*H_)    /* 32   */
#define ML_  (B_*L_)    /* 4096 */
#define QKV_LD 3072
#define KSCALE 0.18033688011112043f   /* log2(e)/8 */

// ---------------- scratch (device globals; no allocation allowed) ----------------
__device__ __align__(128) __half g_Ehi[(size_t)BH_ * L_ * L_];   // [bh][j][i] = exp(S^T), fp16
__device__ __align__(128) float  g_den[(size_t)BH_ * L_];

__device__ __align__(128) __half g_Ahi [(size_t)ML_ * E_];       // z hi, later O
__device__ __align__(128) __half g_Bthi[(size_t)HID_ * E_];      // transposed weights [N,K]
__device__ __align__(128) __half g_QKVhi[(size_t)ML_ * QKV_LD]; // [ML][Q|K'|V] (K pre-scaled)
__device__ __align__(128) __half g_Uh  [(size_t)BH_ * L_ * DH_];
__device__ __align__(128) float  g_biasP[QKV_LD];

// ---------------- ptx helpers (sm_80-compatible PTX only) ----------------
__device__ __forceinline__ uint32_t smem_u32(const void* p) {
    uint32_t a;
    asm("{ .reg .u64 t; cvta.to.shared.u64 t, %1; cvt.u32.u64 %0, t; }" : "=r"(a) : "l"(p));
    return a;
}
__device__ __forceinline__ void cp16(uint32_t saddr, const void* g) {
    asm volatile("cp.async.cg.shared.global [%0], [%1], 16;" :: "r"(saddr), "l"(g));
}
#define CP_COMMIT() asm volatile("cp.async.commit_group;" ::: "memory")
#define CP_WAIT0()  asm volatile("cp.async.wait_group 0;" ::: "memory")
#define CP_WAIT1()  asm volatile("cp.async.wait_group 1;" ::: "memory")

__device__ __forceinline__ void ldsm_x4(uint32_t* r, uint32_t a) {
    asm volatile("ldmatrix.sync.aligned.m8n8.x4.shared.b16 {%0,%1,%2,%3}, [%4];"
        : "=r"(r[0]), "=r"(r[1]), "=r"(r[2]), "=r"(r[3]) : "r"(a));
}
__device__ __forceinline__ void ldsm_x4t(uint32_t* r, uint32_t a) {
    asm volatile("ldmatrix.sync.aligned.m8n8.x4.trans.shared.b16 {%0,%1,%2,%3}, [%4];"
        : "=r"(r[0]), "=r"(r[1]), "=r"(r[2]), "=r"(r[3]) : "r"(a));
}
__device__ __forceinline__ void mma_f16(float* d, const uint32_t* a, const uint32_t* b) {
    asm volatile("mma.sync.aligned.m16n8k16.row.col.f32.f16.f16.f32 "
        "{%0,%1,%2,%3}, {%4,%5,%6,%7}, {%8,%9}, {%0,%1,%2,%3};"
        : "+f"(d[0]), "+f"(d[1]), "+f"(d[2]), "+f"(d[3])
        : "r"(a[0]), "r"(a[1]), "r"(a[2]), "r"(a[3]), "r"(b[0]), "r"(b[1]));
}

__device__ __forceinline__ float gelu_exact(float v) {
    return 0.5f * v * (1.0f + erff(v * 0.7071067811865476f));
}

// ---------------- init: pack bias (bk pre-scaled), init out=b2, zero den ----------------
__global__ void __launch_bounds__(256) init_kernel(const float* __restrict__ bq,
                                                   const float* __restrict__ bk,
                                                   const float* __restrict__ bv,
                                                   const float* __restrict__ b2,
                                                   float* __restrict__ out)
{
    int i = blockIdx.x * 256 + threadIdx.x;
    if (i < 1024)      g_biasP[i] = bq[i];
    else if (i < 2048) g_biasP[i] = bk[i - 1024] * KSCALE;
    else if (i < 3072) g_biasP[i] = bv[i - 2048];
    if (i < ML_) out[i] = b2[0];
    if (i < BH_ * L_) g_den[i] = 0.0f;
}

// ---------------- conversion kernels ----------------
__global__ void __launch_bounds__(256) convert_hi(const float* __restrict__ in,
                                                  __half* __restrict__ hi)
{
    size_t i = (size_t)blockIdx.x * 1024 + threadIdx.x * 4;
    float4 v = *(const float4*)(in + i);
    ((__half2*)(hi + i))[0] = __floats2half2_rn(v.x, v.y);
    ((__half2*)(hi + i))[1] = __floats2half2_rn(v.z, v.w);
}

// Wq/Wk/Wv fp32 [K,N] -> packed Th[N,K] fp16 (Wk pre-scaled by KSCALE)
__global__ void __launch_bounds__(256) transpose_qkv(const float* __restrict__ Wq,
                                                     const float* __restrict__ Wk,
                                                     const float* __restrict__ Wv,
                                                     __half* __restrict__ Th)
{
    __shared__ float sm[32][33];
    const float* W = (blockIdx.z == 0) ? Wq : (blockIdx.z == 1) ? Wk : Wv;
    const float scale = (blockIdx.z == 1) ? KSCALE : 1.0f;
    __half* T = Th + (size_t)blockIdx.z * E_ * E_;
    const int n0 = blockIdx.x * 32, k0 = blockIdx.y * 32;
    const int tx = threadIdx.x & 31, ty = threadIdx.x >> 5;
    #pragma unroll
    for (int i = 0; i < 4; i++)
        sm[ty + i * 8][tx] = W[(size_t)(k0 + ty + i * 8) * E_ + n0 + tx];
    __syncthreads();
    #pragma unroll
    for (int i = 0; i < 4; i++) {
        float v = sm[tx][ty + i * 8] * scale;
        T[(size_t)(n0 + ty + i * 8) * E_ + k0 + tx] = __float2half_rn(v);
    }
}

// W[K,N] fp32 -> Th[N,K] fp16
__global__ void __launch_bounds__(256) transpose_hi(const float* __restrict__ W,
                                                    __half* __restrict__ Th,
                                                    int K, int N)
{
    __shared__ float sm[32][33];
    const int n0 = blockIdx.x * 32, k0 = blockIdx.y * 32;
    const int tx = threadIdx.x & 31, ty = threadIdx.x >> 5;
    #pragma unroll
    for (int i = 0; i < 4; i++)
        sm[ty + i * 8][tx] = W[(size_t)(k0 + ty + i * 8) * N + n0 + tx];
    __syncthreads();
    #pragma unroll
    for (int i = 0; i < 4; i++) {
        float v = sm[tx][ty + i * 8];
        Th[(size_t)(n0 + ty + i * 8) * K + k0 + tx] = __float2half_rn(v);
    }
}

// ---------------- mma.sync fp16 GEMM (1-term: C = Ah @ Bh^T) ----------------
// MODE 0: C = A@B^T + bias -> fp16 out (QKV projection)
// MODE 1: per-head E = exp2(A@B^T) -> fp16 out + atomic denom (QK, K pre-scaled)
// MODE 2: y = gelu(A@B^T + bias); atomicAdd(out[row], y . W2)  (MLP + final)
// default launch bounds -> ptxas picks 128 regs, 2 CTA/SM (measured optimum)
#define G_STAGE 32768   /* Ah 16K | Bh 16K */
#define G_SMEM  (2*G_STAGE + 1024)

template<int MODE>
__global__ void __launch_bounds__(256) gemm_mma(
    const __half* __restrict__ Ahi,
    const __half* __restrict__ Bhi,
    const float* __restrict__ bias, const float* __restrict__ xw,
    __half* __restrict__ Chi,
    float* __restrict__ aux,
    int lda, int ldb, int ldc, int K)
{
    extern __shared__ char smraw[];
    uint32_t smb = smem_u32(smraw);
    smb = (smb + 1023u) & ~1023u;

    const int tid = threadIdx.x, lane = tid & 31, warp = tid >> 5;
    const int wm = warp & 1, wn = warp >> 1;

    size_t aOff = 0, bOff = 0, eOff = 0;
    int bh = 0, bb = 0;
    if (MODE == 1) {
        bh = blockIdx.z; bb = bh >> 4;
        const int h = bh & 15;
        aOff = (size_t)bb * L_ * QKV_LD + 1024 + h * DH_;   // K' vectors
        bOff = (size_t)bb * L_ * QKV_LD + h * DH_;          // Q vectors
        eOff = (size_t)bh * L_ * L_;
    }
    const int m0g = blockIdx.y * 128, n0g = blockIdx.x * 128;

    const char* gA = (const char*)(Ahi + aOff + (size_t)m0g * lda);
    const char* gB = (const char*)(Bhi + bOff + (size_t)n0g * ldb);

    const int nCh = K >> 6;
    float acc[4][4][4] = {};

    auto loadStage = [&](int st, int k0) {
        #pragma unroll
        for (int arr = 0; arr < 2; arr++) {
            const char* base = (arr == 0) ? gA : gB;
            const int ld2 = ((arr == 0) ? lda : ldb) * 2;
            const uint32_t sb = smb + st * G_STAGE + arr * 16384;
            #pragma unroll
            for (int q = 0; q < 4; q++) {
                int id = tid + q * 256;
                int row = id >> 3, c16 = (id & 7) << 4;
                uint32_t sa = sb + row * 128 + (c16 ^ ((row & 7) << 4));
                cp16(sa, base + (size_t)row * ld2 + k0 * 2 + c16);
            }
        }
    };

    loadStage(0, 0);
    CP_COMMIT();

    for (int c = 0; c < nCh; c++) {
        const int st = c & 1;
        if (c + 1 < nCh) { loadStage(st ^ 1, (c + 1) << 6); CP_COMMIT(); CP_WAIT1(); }
        else             { CP_WAIT0(); }
        __syncthreads();

        const uint32_t sA = smb + st * G_STAGE;
        const uint32_t sB = sA + 16384;
        #pragma unroll
        for (int s = 0; s < 4; s++) {
            const int kb = s * 32;
            uint32_t aH[4][4], bH[4][2];
            const int lr = lane & 15, lc = lane >> 4;
            #pragma unroll
            for (int mt = 0; mt < 4; mt++) {
                int r = wm * 64 + mt * 16 + lr;
                int cb = kb + lc * 16;
                uint32_t ad = sA + r * 128 + (cb ^ ((r & 7) << 4));
                ldsm_x4(aH[mt], ad);
            }
            // B: two x4 loads, each covering a pair of n-tiles
            #pragma unroll
            for (int np = 0; np < 2; np++) {
                int r = wn * 32 + np * 16 + ((lane >> 4) << 3) + (lane & 7);
                int cb = kb + (((lane >> 3) & 1) << 4);
                uint32_t bd = sB + r * 128 + (cb ^ ((r & 7) << 4));
                uint32_t t[4];
                ldsm_x4(t, bd);
                bH[np * 2 + 0][0] = t[0]; bH[np * 2 + 0][1] = t[1];
                bH[np * 2 + 1][0] = t[2]; bH[np * 2 + 1][1] = t[3];
            }
            #pragma unroll
            for (int mt = 0; mt < 4; mt++)
                #pragma unroll
                for (int nt = 0; nt < 4; nt++)
                    mma_f16(acc[mt][nt], aH[mt], bH[nt]);
        }
        __syncthreads();
    }

    // ---- epilogues ----
    if (MODE == 0) {
        #pragma unroll
        for (int mt = 0; mt < 4; mt++) {
            #pragma unroll
            for (int nt = 0; nt < 4; nt++) {
                const int row = m0g + wm * 64 + mt * 16 + (lane >> 2);
                const int col = n0g + wn * 32 + nt * 8 + 2 * (lane & 3);
                float b0 = __ldg(bias + col), b1 = __ldg(bias + col + 1);
                *(__half2*)(Chi + (size_t)row * ldc + col) = __halves2half2(
                    __float2half_rn(acc[mt][nt][0] + b0),
                    __float2half_rn(acc[mt][nt][1] + b1));
                *(__half2*)(Chi + (size_t)(row + 8) * ldc + col) = __halves2half2(
                    __float2half_rn(acc[mt][nt][2] + b0),
                    __float2half_rn(acc[mt][nt][3] + b1));
            }
        }
    } else if (MODE == 1) {
        const float* xb = xw + bb * L_;
        float xc[4][2];
        #pragma unroll
        for (int nt = 0; nt < 4; nt++) {
            int col = n0g + wn * 32 + nt * 8 + 2 * (lane & 3);
            xc[nt][0] = __ldg(xb + col);
            xc[nt][1] = __ldg(xb + col + 1);
        }
        #pragma unroll
        for (int mt = 0; mt < 4; mt++) {
            const int rg = m0g + wm * 64 + mt * 16 + (lane >> 2);
            float p0 = 0.0f, p8 = 0.0f;
            #pragma unroll
            for (int nt = 0; nt < 4; nt++) {
                const int col = n0g + wn * 32 + nt * 8 + 2 * (lane & 3);
                float e0 = exp2f(acc[mt][nt][0]);
                float e1 = exp2f(acc[mt][nt][1]);
                float e2 = exp2f(acc[mt][nt][2]);
                float e3 = exp2f(acc[mt][nt][3]);
                *(__half2*)(Chi + eOff + (size_t)rg * ldc + col) =
                    __halves2half2(__float2half_rn(e0), __float2half_rn(e1));
                *(__half2*)(Chi + eOff + (size_t)(rg + 8) * ldc + col) =
                    __halves2half2(__float2half_rn(e2), __float2half_rn(e3));
                p0 += xc[nt][0] * e0 + xc[nt][1] * e1;
                p8 += xc[nt][0] * e2 + xc[nt][1] * e3;
            }
            p0 += __shfl_xor_sync(0xffffffffu, p0, 1);
            p0 += __shfl_xor_sync(0xffffffffu, p0, 2);
            p8 += __shfl_xor_sync(0xffffffffu, p8, 1);
            p8 += __shfl_xor_sync(0xffffffffu, p8, 2);
            if ((lane & 3) == 0) {
                atomicAdd(aux + (size_t)bh * L_ + rg,     p0);
                atomicAdd(aux + (size_t)bh * L_ + rg + 8, p8);
            }
        }
    } else {  // MODE == 2
        #pragma unroll
        for (int mt = 0; mt < 4; mt++) {
            const int row = m0g + wm * 64 + mt * 16 + (lane >> 2);
            float p0 = 0.0f, p8 = 0.0f;
            #pragma unroll
            for (int nt = 0; nt < 4; nt++) {
                const int col = n0g + wn * 32 + nt * 8 + 2 * (lane & 3);
                float b0 = __ldg(bias + col), b1 = __ldg(bias + col + 1);
                float w0 = __ldg(xw + col),  w1 = __ldg(xw + col + 1);
                float v0 = gelu_exact(acc[mt][nt][0] + b0);
                float v1 = gelu_exact(acc[mt][nt][1] + b1);
                float v2 = gelu_exact(acc[mt][nt][2] + b0);
                float v3 = gelu_exact(acc[mt][nt][3] + b1);
                p0 += v0 * w0 + v1 * w1;
                p8 += v2 * w0 + v3 * w1;
            }
            p0 += __shfl_xor_sync(0xffffffffu, p0, 1);
            p0 += __shfl_xor_sync(0xffffffffu, p0, 2);
            p8 += __shfl_xor_sync(0xffffffffu, p8, 1);
            p8 += __shfl_xor_sync(0xffffffffu, p8, 2);
            if ((lane & 3) == 0) {
                atomicAdd(aux + row,     p0);
                atomicAdd(aux + row + 8, p8);
            }
        }
    }
}

// ---------------- U kernel: U[bh][j][d] = x_j * V[b,j,h,d] / den[bh][j] (fp16) ----------------
__global__ void __launch_bounds__(256) u_kernel(const float* __restrict__ x)
{
    int gid = blockIdx.x * 256 + threadIdx.x;
    int d = gid & 63;
    int row = gid >> 6;                          // bh*L + j
    int bh = row >> 11, j = row & (L_ - 1);
    int b = bh >> 4, h = bh & 15;
    float den = g_den[row];
    size_t vo = ((size_t)b * L_ + j) * QKV_LD + 2048 + h * DH_ + d;
    float v = __half2float(g_QKVhi[vo]);
    float u = __ldg(x + b * L_ + j) * v / den;
    g_Uh[(size_t)row * DH_ + d] = __float2half_rn(u);
}

// ---------------- attention output: O[i,d] = x_i * sum_j E[j,i]*U[j,d] ----------------
#define AT_STAGE 24576  /* Eh 16K | Uh 8K */
#define AT_SMEM  (2*AT_STAGE + 1024)

__global__ void __launch_bounds__(256) attn_mma(const float* __restrict__ x)
{
    extern __shared__ char smraw[];
    uint32_t smb = smem_u32(smraw);
    smb = (smb + 1023u) & ~1023u;

    const int tid = threadIdx.x, lane = tid & 31, warp = tid >> 5;
    const int wi = warp & 3, wd = warp >> 2;     // warp tile: 32 i x 32 d
    const int bh = blockIdx.y, b = bh >> 4, h = bh & 15;
    const int i0 = blockIdx.x * 128;

    const char* Ehb = (const char*)(g_Ehi + (size_t)bh * L_ * L_);
    const char* Uhb = (const char*)(g_Uh + (size_t)bh * L_ * DH_);

    float acc[2][4][4] = {};

    auto loadStage = [&](int st, int j0) {
        const uint32_t sb = smb + st * AT_STAGE;
        #pragma unroll
        for (int q = 0; q < 4; q++) {
            int id = tid + q * 256;
            int row = id >> 4, c16 = (id & 15) << 4;
            uint32_t soff = row * 256 + (c16 ^ ((row & 7) << 4));
            size_t go = (size_t)(j0 + row) * (L_ * 2) + (size_t)i0 * 2 + c16;
            cp16(sb + soff, Ehb + go);
        }
        #pragma unroll
        for (int q = 0; q < 2; q++) {
            int id = tid + q * 256;
            int row = id >> 3, c16 = (id & 7) << 4;
            uint32_t uoff = row * 128 + (c16 ^ ((row & 7) << 4));
            cp16(sb + 16384 + uoff, Uhb + (size_t)(j0 + row) * 128 + c16);
        }
    };

    loadStage(0, 0);
    CP_COMMIT();

    for (int c = 0; c < L_ / 64; c++) {
        const int st = c & 1;
        if (c + 1 < L_ / 64) { loadStage(st ^ 1, (c + 1) * 64); CP_COMMIT(); CP_WAIT1(); }
        else                 { CP_WAIT0(); }
        __syncthreads();

        const uint32_t sb = smb + st * AT_STAGE;
        #pragma unroll
        for (int s = 0; s < 4; s++) {
            const int k0 = s * 16;
            uint32_t eH[2][4], uH[4][2];
            {
                const int r = k0 + (lane & 7) + ((lane >> 4) << 3);
                const int cbl = (((lane >> 3) & 1) << 4);
                #pragma unroll
                for (int mt = 0; mt < 2; mt++) {
                    int cb = (wi * 32 + mt * 16) * 2 + cbl;
                    uint32_t ad = sb + r * 256 + (cb ^ ((r & 7) << 4));
                    ldsm_x4t(eH[mt], ad);
                }
            }
            // U: two x4t loads, each covering a pair of n(d)-tiles
            {
                const int r = k0 + (lane & 7) + (((lane >> 3) & 1) << 3);
                #pragma unroll
                for (int np = 0; np < 2; np++) {
                    int cb = (wd * 32 + np * 16 + ((lane >> 4) << 3)) * 2;
                    uint32_t ud = sb + 16384 + r * 128 + (cb ^ ((r & 7) << 4));
                    uint32_t t[4];
                    ldsm_x4t(t, ud);
                    uH[np * 2 + 0][0] = t[0]; uH[np * 2 + 0][1] = t[1];
                    uH[np * 2 + 1][0] = t[2]; uH[np * 2 + 1][1] = t[3];
                }
            }
            #pragma unroll
            for (int mt = 0; mt < 2; mt++)
                #pragma unroll
                for (int nt = 0; nt < 4; nt++)
                    mma_f16(acc[mt][nt], eH[mt], uH[nt]);
        }
        __syncthreads();
    }

    // epilogue: O fp16 hi-only into g_Ahi [ML][E]
    #pragma unroll
    for (int mt = 0; mt < 2; mt++) {
        #pragma unroll
        for (int nt = 0; nt < 4; nt++) {
            const int row = i0 + wi * 32 + mt * 16 + (lane >> 2);
            const int col = h * DH_ + wd * 32 + nt * 8 + 2 * (lane & 3);
            float x0 = __ldg(x + b * L_ + row);
            float x1 = __ldg(x + b * L_ + row + 8);
            size_t r0 = ((size_t)b * L_ + row) * E_ + col;
            size_t r8 = ((size_t)b * L_ + row + 8) * E_ + col;
            *(__half2*)(g_Ahi + r0) = __halves2half2(
                __float2half_rn(acc[mt][nt][0] * x0),
                __float2half_rn(acc[mt][nt][1] * x0));
            *(__half2*)(g_Ahi + r8) = __halves2half2(
                __float2half_rn(acc[mt][nt][2] * x1),
                __float2half_rn(acc[mt][nt][3] * x1));
        }
    }
}

// ---------------- launch ----------------
extern "C" void kernel_launch(void* const* d_in, const int* in_sizes, int n_in,
                              void* d_out, int out_size)
{
    (void)in_sizes; (void)n_in; (void)out_size;
    const float* x  = (const float*)d_in[0];
    const float* z  = (const float*)d_in[1];
    const float* Wq = (const float*)d_in[2];
    const float* bq = (const float*)d_in[3];
    const float* Wk = (const float*)d_in[4];
    const float* bk = (const float*)d_in[5];
    const float* Wv = (const float*)d_in[6];
    const float* bv = (const float*)d_in[7];
    const float* W1 = (const float*)d_in[8];
    const float* b1 = (const float*)d_in[9];
    const float* W2 = (const float*)d_in[10];
    const float* b2 = (const float*)d_in[11];
    float* out = (float*)d_out;

    __half *pAhi, *pBhi, *pQKVhi, *pEhi;
    float *pDen, *pBiasP;
    cudaGetSymbolAddress((void**)&pAhi, g_Ahi);
    cudaGetSymbolAddress((void**)&pBhi, g_Bthi);
    cudaGetSymbolAddress((void**)&pQKVhi, g_QKVhi);
    cudaGetSymbolAddress((void**)&pEhi, g_Ehi);
    cudaGetSymbolAddress((void**)&pDen, g_den);
    cudaGetSymbolAddress((void**)&pBiasP, g_biasP);

    cudaFuncSetAttribute(gemm_mma<0>, cudaFuncAttributeMaxDynamicSharedMemorySize, G_SMEM);
    cudaFuncSetAttribute(gemm_mma<1>, cudaFuncAttributeMaxDynamicSharedMemorySize, G_SMEM);
    cudaFuncSetAttribute(gemm_mma<2>, cudaFuncAttributeMaxDynamicSharedMemorySize, G_SMEM);
    cudaFuncSetAttribute(attn_mma, cudaFuncAttributeMaxDynamicSharedMemorySize, AT_SMEM);

    const size_t nZ = (size_t)ML_ * E_;

    // init: packed bias (bk pre-scaled), out = b2, den = 0
    init_kernel<<<256, 256>>>(bq, bk, bv, b2, out);

    // convert z -> fp16 hi
    convert_hi<<<nZ / 1024, 256>>>(z, pAhi);

    // pack transposed QKV weights (fused; Wk pre-scaled by log2e/8)
    transpose_qkv<<<dim3(E_ / 32, E_ / 32, 3), 256>>>(Wq, Wk, Wv, pBhi);

    // fused QKV projection -> fp16 [ML][3072]  (1-term, hi out)
    gemm_mma<0><<<dim3(QKV_LD / 128, ML_ / 128), 256, G_SMEM>>>(
        pAhi, pBhi, pBiasP, nullptr, pQKVhi, nullptr,
        E_, E_, QKV_LD, E_);

    // QK: E = exp2(K'_j . Q_i) fp16 + atomic denom  (1-term)
    gemm_mma<1><<<dim3(L_ / 128, L_ / 128, BH_), 256, G_SMEM>>>(
        pQKVhi, pQKVhi, nullptr, x, pEhi, pDen,
        QKV_LD, QKV_LD, L_, DH_);

    // U = x_j * V / den, fp16
    u_kernel<<<(BH_ * L_ * DH_) / 256, 256>>>(x);

    // attention output -> O fp16 (hi only, into g_Ahi)  (1-term)
    attn_mma<<<dim3(L_ / 128, BH_), 256, AT_SMEM>>>(x);

    // W1 transpose (hi only)
    transpose_hi<<<dim3(HID_ / 32, E_ / 32), 256>>>(W1, pBhi, E_, HID_);

    // MLP1 + fused W2 reduction -> out (atomic, 1-term)
    gemm_mma<2><<<dim3(HID_ / 128, ML_ / 128), 256, G_SMEM>>>(
        pAhi, pBhi, b1, W2, nullptr, out,
        E_, E_, 0, E_);
}

// round 17
// speedup vs baseline: 1.2858x; 1.0048x over previous
#include <cuda_runtime.h>
#include <cuda_fp16.h>
#include <math.h>
#include <stdint.h>

#define B_   2
#define L_   2048
#define E_   1024
#define H_   16
#define DH_  64
#define HID_ 4096
#define BH_  (B_*H_)    /* 32   */
#define ML_  (B_*L_)    /* 4096 */
#define QKV_LD 3072
#define KSCALE 0.18033688011112043f   /* log2(e)/8 */

// ---------------- scratch (device globals; no allocation allowed) ----------------
__device__ __align__(128) __half g_Ehi[(size_t)BH_ * L_ * L_];   // [bh][j][i] = exp(S^T), fp16
__device__ __align__(128) float  g_den[(size_t)BH_ * L_];

__device__ __align__(128) __half g_Ahi [(size_t)ML_ * E_];       // z hi, later O
__device__ __align__(128) __half g_Bthi[(size_t)HID_ * E_];      // transposed weights [N,K]
__device__ __align__(128) __half g_QKVhi[(size_t)ML_ * QKV_LD]; // [ML][Q|K'|V] (K pre-scaled)
__device__ __align__(128) __half g_Uh  [(size_t)BH_ * L_ * DH_];
__device__ __align__(128) float  g_biasP[QKV_LD];

// ---------------- ptx helpers (sm_80-compatible PTX only) ----------------
__device__ __forceinline__ uint32_t smem_u32(const void* p) {
    uint32_t a;
    asm("{ .reg .u64 t; cvta.to.shared.u64 t, %1; cvt.u32.u64 %0, t; }" : "=r"(a) : "l"(p));
    return a;
}
__device__ __forceinline__ void cp16(uint32_t saddr, const void* g) {
    asm volatile("cp.async.cg.shared.global [%0], [%1], 16;" :: "r"(saddr), "l"(g));
}
#define CP_COMMIT() asm volatile("cp.async.commit_group;" ::: "memory")
#define CP_WAIT0()  asm volatile("cp.async.wait_group 0;" ::: "memory")
#define CP_WAIT1()  asm volatile("cp.async.wait_group 1;" ::: "memory")

__device__ __forceinline__ void ldsm_x4(uint32_t* r, uint32_t a) {
    asm volatile("ldmatrix.sync.aligned.m8n8.x4.shared.b16 {%0,%1,%2,%3}, [%4];"
        : "=r"(r[0]), "=r"(r[1]), "=r"(r[2]), "=r"(r[3]) : "r"(a));
}
__device__ __forceinline__ void ldsm_x4t(uint32_t* r, uint32_t a) {
    asm volatile("ldmatrix.sync.aligned.m8n8.x4.trans.shared.b16 {%0,%1,%2,%3}, [%4];"
        : "=r"(r[0]), "=r"(r[1]), "=r"(r[2]), "=r"(r[3]) : "r"(a));
}
__device__ __forceinline__ void mma_f16(float* d, const uint32_t* a, const uint32_t* b) {
    asm volatile("mma.sync.aligned.m16n8k16.row.col.f32.f16.f16.f32 "
        "{%0,%1,%2,%3}, {%4,%5,%6,%7}, {%8,%9}, {%0,%1,%2,%3};"
        : "+f"(d[0]), "+f"(d[1]), "+f"(d[2]), "+f"(d[3])
        : "r"(a[0]), "r"(a[1]), "r"(a[2]), "r"(a[3]), "r"(b[0]), "r"(b[1]));
}

__device__ __forceinline__ float gelu_exact(float v) {
    return 0.5f * v * (1.0f + erff(v * 0.7071067811865476f));
}

// ---------------- init: pack bias (bk pre-scaled), init out=b2, zero den ----------------
__global__ void __launch_bounds__(256) init_kernel(const float* __restrict__ bq,
                                                   const float* __restrict__ bk,
                                                   const float* __restrict__ bv,
                                                   const float* __restrict__ b2,
                                                   float* __restrict__ out)
{
    int i = blockIdx.x * 256 + threadIdx.x;
    if (i < 1024)      g_biasP[i] = bq[i];
    else if (i < 2048) g_biasP[i] = bk[i - 1024] * KSCALE;
    else if (i < 3072) g_biasP[i] = bv[i - 2048];
    if (i < ML_) out[i] = b2[0];
    if (i < BH_ * L_) g_den[i] = 0.0f;
}

// ---------------- conversion kernels ----------------
__global__ void __launch_bounds__(256) convert_hi(const float* __restrict__ in,
                                                  __half* __restrict__ hi)
{
    size_t i = (size_t)blockIdx.x * 1024 + threadIdx.x * 4;
    float4 v = *(const float4*)(in + i);
    ((__half2*)(hi + i))[0] = __floats2half2_rn(v.x, v.y);
    ((__half2*)(hi + i))[1] = __floats2half2_rn(v.z, v.w);
}

// 64x64-tile transpose: W[K,N] fp32 -> T[N,K] fp16 (optional scale)
// Wq/Wk/Wv packed variant: blockIdx.z selects matrix (Wk scaled by KSCALE)
__global__ void __launch_bounds__(256) transpose_qkv(const float* __restrict__ Wq,
                                                     const float* __restrict__ Wk,
                                                     const float* __restrict__ Wv,
                                                     __half* __restrict__ Th)
{
    __shared__ float sm[64][65];
    const float* W = (blockIdx.z == 0) ? Wq : (blockIdx.z == 1) ? Wk : Wv;
    const float scale = (blockIdx.z == 1) ? KSCALE : 1.0f;
    __half* T = Th + (size_t)blockIdx.z * E_ * E_;
    const int n0 = blockIdx.x * 64, k0 = blockIdx.y * 64;
    #pragma unroll
    for (int p = 0; p < 4; p++) {
        int r  = (threadIdx.x >> 4) + p * 16;
        int c4 = (threadIdx.x & 15) * 4;
        float4 v = *(const float4*)(W + (size_t)(k0 + r) * E_ + n0 + c4);
        sm[r][c4] = v.x; sm[r][c4 + 1] = v.y; sm[r][c4 + 2] = v.z; sm[r][c4 + 3] = v.w;
    }
    __syncthreads();
    #pragma unroll
    for (int p = 0; p < 8; p++) {
        int n = (threadIdx.x >> 5) + p * 8;
        int k = (threadIdx.x & 31) * 2;
        *(__half2*)(T + (size_t)(n0 + n) * E_ + k0 + k) =
            __floats2half2_rn(sm[k][n] * scale, sm[k + 1][n] * scale);
    }
}

__global__ void __launch_bounds__(256) transpose64(const float* __restrict__ W,
                                                   __half* __restrict__ T,
                                                   int K, int N)
{
    __shared__ float sm[64][65];
    const int n0 = blockIdx.x * 64, k0 = blockIdx.y * 64;
    #pragma unroll
    for (int p = 0; p < 4; p++) {
        int r  = (threadIdx.x >> 4) + p * 16;
        int c4 = (threadIdx.x & 15) * 4;
        float4 v = *(const float4*)(W + (size_t)(k0 + r) * N + n0 + c4);
        sm[r][c4] = v.x; sm[r][c4 + 1] = v.y; sm[r][c4 + 2] = v.z; sm[r][c4 + 3] = v.w;
    }
    __syncthreads();
    #pragma unroll
    for (int p = 0; p < 8; p++) {
        int n = (threadIdx.x >> 5) + p * 8;
        int k = (threadIdx.x & 31) * 2;
        *(__half2*)(T + (size_t)(n0 + n) * K + k0 + k) =
            __floats2half2_rn(sm[k][n], sm[k + 1][n]);
    }
}

// ---------------- mma.sync fp16 GEMM (1-term, 3-stage pipeline) ----------------
// MODE 0: C = A@B^T + bias -> fp16 out (QKV projection)
// MODE 1: per-head E = exp2(A@B^T) -> fp16 out + atomic denom (QK, K pre-scaled)
// MODE 2: y = gelu(A@B^T + bias); atomicAdd(out[row], y . W2)  (MLP + final)
#define G_STAGE 32768   /* Ah 16K | Bh 16K */
#define G_SMEM  (3*G_STAGE + 1024)

template<int MODE>
__global__ void __launch_bounds__(256) gemm_mma(
    const __half* __restrict__ Ahi,
    const __half* __restrict__ Bhi,
    const float* __restrict__ bias, const float* __restrict__ xw,
    __half* __restrict__ Chi,
    float* __restrict__ aux,
    int lda, int ldb, int ldc, int K)
{
    extern __shared__ char smraw[];
    uint32_t smb = smem_u32(smraw);
    smb = (smb + 1023u) & ~1023u;

    const int tid = threadIdx.x, lane = tid & 31, warp = tid >> 5;
    const int wm = warp & 1, wn = warp >> 1;

    size_t aOff = 0, bOff = 0, eOff = 0;
    int bh = 0, bb = 0;
    if (MODE == 1) {
        bh = blockIdx.z; bb = bh >> 4;
        const int h = bh & 15;
        aOff = (size_t)bb * L_ * QKV_LD + 1024 + h * DH_;   // K' vectors
        bOff = (size_t)bb * L_ * QKV_LD + h * DH_;          // Q vectors
        eOff = (size_t)bh * L_ * L_;
    }
    const int m0g = blockIdx.y * 128, n0g = blockIdx.x * 128;

    const char* gA = (const char*)(Ahi + aOff + (size_t)m0g * lda);
    const char* gB = (const char*)(Bhi + bOff + (size_t)n0g * ldb);

    const int nCh = K >> 6;
    float acc[4][4][4] = {};

    auto loadStage = [&](int st, int k0) {
        #pragma unroll
        for (int arr = 0; arr < 2; arr++) {
            const char* base = (arr == 0) ? gA : gB;
            const int ld2 = ((arr == 0) ? lda : ldb) * 2;
            const uint32_t sb = smb + st * G_STAGE + arr * 16384;
            #pragma unroll
            for (int q = 0; q < 4; q++) {
                int id = tid + q * 256;
                int row = id >> 3, c16 = (id & 7) << 4;
                uint32_t sa = sb + row * 128 + (c16 ^ ((row & 7) << 4));
                cp16(sa, base + (size_t)row * ld2 + k0 * 2 + c16);
            }
        }
    };

    loadStage(0, 0);
    CP_COMMIT();
    if (nCh > 1) { loadStage(1, 1 << 6); CP_COMMIT(); }

    for (int c = 0; c < nCh; c++) {
        if (c + 1 < nCh) { CP_WAIT1(); } else { CP_WAIT0(); }
        __syncthreads();

        const uint32_t sA = smb + (c % 3) * G_STAGE;
        const uint32_t sB = sA + 16384;
        #pragma unroll
        for (int s = 0; s < 4; s++) {
            const int kb = s * 32;
            uint32_t aH[4][4], bH[4][2];
            const int lr = lane & 15, lc = lane >> 4;
            #pragma unroll
            for (int mt = 0; mt < 4; mt++) {
                int r = wm * 64 + mt * 16 + lr;
                int cb = kb + lc * 16;
                uint32_t ad = sA + r * 128 + (cb ^ ((r & 7) << 4));
                ldsm_x4(aH[mt], ad);
            }
            #pragma unroll
            for (int np = 0; np < 2; np++) {
                int r = wn * 32 + np * 16 + ((lane >> 4) << 3) + (lane & 7);
                int cb = kb + (((lane >> 3) & 1) << 4);
                uint32_t bd = sB + r * 128 + (cb ^ ((r & 7) << 4));
                uint32_t t[4];
                ldsm_x4(t, bd);
                bH[np * 2 + 0][0] = t[0]; bH[np * 2 + 0][1] = t[1];
                bH[np * 2 + 1][0] = t[2]; bH[np * 2 + 1][1] = t[3];
            }
            #pragma unroll
            for (int mt = 0; mt < 4; mt++)
                #pragma unroll
                for (int nt = 0; nt < 4; nt++)
                    mma_f16(acc[mt][nt], aH[mt], bH[nt]);
        }
        // prefetch chunk c+2 into stage (c+2)%3 (last read at iteration c-1,
        // protected by this iteration's top-of-loop __syncthreads)
        if (c + 2 < nCh) { loadStage((c + 2) % 3, (c + 2) << 6); CP_COMMIT(); }
    }

    // ---- epilogues ----
    if (MODE == 0) {
        #pragma unroll
        for (int mt = 0; mt < 4; mt++) {
            #pragma unroll
            for (int nt = 0; nt < 4; nt++) {
                const int row = m0g + wm * 64 + mt * 16 + (lane >> 2);
                const int col = n0g + wn * 32 + nt * 8 + 2 * (lane & 3);
                float b0 = __ldg(bias + col), b1 = __ldg(bias + col + 1);
                *(__half2*)(Chi + (size_t)row * ldc + col) = __halves2half2(
                    __float2half_rn(acc[mt][nt][0] + b0),
                    __float2half_rn(acc[mt][nt][1] + b1));
                *(__half2*)(Chi + (size_t)(row + 8) * ldc + col) = __halves2half2(
                    __float2half_rn(acc[mt][nt][2] + b0),
                    __float2half_rn(acc[mt][nt][3] + b1));
            }
        }
    } else if (MODE == 1) {
        const float* xb = xw + bb * L_;
        float xc[4][2];
        #pragma unroll
        for (int nt = 0; nt < 4; nt++) {
            int col = n0g + wn * 32 + nt * 8 + 2 * (lane & 3);
            xc[nt][0] = __ldg(xb + col);
            xc[nt][1] = __ldg(xb + col + 1);
        }
        #pragma unroll
        for (int mt = 0; mt < 4; mt++) {
            const int rg = m0g + wm * 64 + mt * 16 + (lane >> 2);
            float p0 = 0.0f, p8 = 0.0f;
            #pragma unroll
            for (int nt = 0; nt < 4; nt++) {
                const int col = n0g + wn * 32 + nt * 8 + 2 * (lane & 3);
                float e0 = exp2f(acc[mt][nt][0]);
                float e1 = exp2f(acc[mt][nt][1]);
                float e2 = exp2f(acc[mt][nt][2]);
                float e3 = exp2f(acc[mt][nt][3]);
                *(__half2*)(Chi + eOff + (size_t)rg * ldc + col) =
                    __halves2half2(__float2half_rn(e0), __float2half_rn(e1));
                *(__half2*)(Chi + eOff + (size_t)(rg + 8) * ldc + col) =
                    __halves2half2(__float2half_rn(e2), __float2half_rn(e3));
                p0 += xc[nt][0] * e0 + xc[nt][1] * e1;
                p8 += xc[nt][0] * e2 + xc[nt][1] * e3;
            }
            p0 += __shfl_xor_sync(0xffffffffu, p0, 1);
            p0 += __shfl_xor_sync(0xffffffffu, p0, 2);
            p8 += __shfl_xor_sync(0xffffffffu, p8, 1);
            p8 += __shfl_xor_sync(0xffffffffu, p8, 2);
            if ((lane & 3) == 0) {
                atomicAdd(aux + (size_t)bh * L_ + rg,     p0);
                atomicAdd(aux + (size_t)bh * L_ + rg + 8, p8);
            }
        }
    } else {  // MODE == 2
        #pragma unroll
        for (int mt = 0; mt < 4; mt++) {
            const int row = m0g + wm * 64 + mt * 16 + (lane >> 2);
            float p0 = 0.0f, p8 = 0.0f;
            #pragma unroll
            for (int nt = 0; nt < 4; nt++) {
                const int col = n0g + wn * 32 + nt * 8 + 2 * (lane & 3);
                float b0 = __ldg(bias + col), b1 = __ldg(bias + col + 1);
                float w0 = __ldg(xw + col),  w1 = __ldg(xw + col + 1);
                float v0 = gelu_exact(acc[mt][nt][0] + b0);
                float v1 = gelu_exact(acc[mt][nt][1] + b1);
                float v2 = gelu_exact(acc[mt][nt][2] + b0);
                float v3 = gelu_exact(acc[mt][nt][3] + b1);
                p0 += v0 * w0 + v1 * w1;
                p8 += v2 * w0 + v3 * w1;
            }
            p0 += __shfl_xor_sync(0xffffffffu, p0, 1);
            p0 += __shfl_xor_sync(0xffffffffu, p0, 2);
            p8 += __shfl_xor_sync(0xffffffffu, p8, 1);
            p8 += __shfl_xor_sync(0xffffffffu, p8, 2);
            if ((lane & 3) == 0) {
                atomicAdd(aux + row,     p0);
                atomicAdd(aux + row + 8, p8);
            }
        }
    }
}

// ---------------- U kernel: U[bh][j][d] = x_j * V[b,j,h,d] / den[bh][j] (fp16) ----------------
__global__ void __launch_bounds__(256) u_kernel(const float* __restrict__ x)
{
    int gid = blockIdx.x * 256 + threadIdx.x;
    int d = gid & 63;
    int row = gid >> 6;                          // bh*L + j
    int bh = row >> 11, j = row & (L_ - 1);
    int b = bh >> 4, h = bh & 15;
    float den = g_den[row];
    size_t vo = ((size_t)b * L_ + j) * QKV_LD + 2048 + h * DH_ + d;
    float v = __half2float(g_QKVhi[vo]);
    float u = __ldg(x + b * L_ + j) * v / den;
    g_Uh[(size_t)row * DH_ + d] = __float2half_rn(u);
}

// ---------------- attention output: O[i,d] = x_i * sum_j E[j,i]*U[j,d] (3-stage) ----------------
#define AT_STAGE 24576  /* Eh 16K | Uh 8K */
#define AT_SMEM  (3*AT_STAGE + 1024)

__global__ void __launch_bounds__(256) attn_mma(const float* __restrict__ x)
{
    extern __shared__ char smraw[];
    uint32_t smb = smem_u32(smraw);
    smb = (smb + 1023u) & ~1023u;

    const int tid = threadIdx.x, lane = tid & 31, warp = tid >> 5;
    const int wi = warp & 3, wd = warp >> 2;     // warp tile: 32 i x 32 d
    const int bh = blockIdx.y, b = bh >> 4, h = bh & 15;
    const int i0 = blockIdx.x * 128;

    const char* Ehb = (const char*)(g_Ehi + (size_t)bh * L_ * L_);
    const char* Uhb = (const char*)(g_Uh + (size_t)bh * L_ * DH_);

    float acc[2][4][4] = {};

    auto loadStage = [&](int st, int j0) {
        const uint32_t sb = smb + st * AT_STAGE;
        #pragma unroll
        for (int q = 0; q < 4; q++) {
            int id = tid + q * 256;
            int row = id >> 4, c16 = (id & 15) << 4;
            uint32_t soff = row * 256 + (c16 ^ ((row & 7) << 4));
            size_t go = (size_t)(j0 + row) * (L_ * 2) + (size_t)i0 * 2 + c16;
            cp16(sb + soff, Ehb + go);
        }
        #pragma unroll
        for (int q = 0; q < 2; q++) {
            int id = tid + q * 256;
            int row = id >> 3, c16 = (id & 7) << 4;
            uint32_t uoff = row * 128 + (c16 ^ ((row & 7) << 4));
            cp16(sb + 16384 + uoff, Uhb + (size_t)(j0 + row) * 128 + c16);
        }
    };

    const int nCh = L_ / 64;
    loadStage(0, 0);
    CP_COMMIT();
    loadStage(1, 64);
    CP_COMMIT();

    for (int c = 0; c < nCh; c++) {
        if (c + 1 < nCh) { CP_WAIT1(); } else { CP_WAIT0(); }
        __syncthreads();

        const uint32_t sb = smb + (c % 3) * AT_STAGE;
        #pragma unroll
        for (int s = 0; s < 4; s++) {
            const int k0 = s * 16;
            uint32_t eH[2][4], uH[4][2];
            {
                const int r = k0 + (lane & 7) + ((lane >> 4) << 3);
                const int cbl = (((lane >> 3) & 1) << 4);
                #pragma unroll
                for (int mt = 0; mt < 2; mt++) {
                    int cb = (wi * 32 + mt * 16) * 2 + cbl;
                    uint32_t ad = sb + r * 256 + (cb ^ ((r & 7) << 4));
                    ldsm_x4t(eH[mt], ad);
                }
            }
            {
                const int r = k0 + (lane & 7) + (((lane >> 3) & 1) << 3);
                #pragma unroll
                for (int np = 0; np < 2; np++) {
                    int cb = (wd * 32 + np * 16 + ((lane >> 4) << 3)) * 2;
                    uint32_t ud = sb + 16384 + r * 128 + (cb ^ ((r & 7) << 4));
                    uint32_t t[4];
                    ldsm_x4t(t, ud);
                    uH[np * 2 + 0][0] = t[0]; uH[np * 2 + 0][1] = t[1];
                    uH[np * 2 + 1][0] = t[2]; uH[np * 2 + 1][1] = t[3];
                }
            }
            #pragma unroll
            for (int mt = 0; mt < 2; mt++)
                #pragma unroll
                for (int nt = 0; nt < 4; nt++)
                    mma_f16(acc[mt][nt], eH[mt], uH[nt]);
        }
        if (c + 2 < nCh) { loadStage((c + 2) % 3, (c + 2) * 64); CP_COMMIT(); }
    }

    // epilogue: O fp16 hi-only into g_Ahi [ML][E]
    #pragma unroll
    for (int mt = 0; mt < 2; mt++) {
        #pragma unroll
        for (int nt = 0; nt < 4; nt++) {
            const int row = i0 + wi * 32 + mt * 16 + (lane >> 2);
            const int col = h * DH_ + wd * 32 + nt * 8 + 2 * (lane & 3);
            float x0 = __ldg(x + b * L_ + row);
            float x1 = __ldg(x + b * L_ + row + 8);
            size_t r0 = ((size_t)b * L_ + row) * E_ + col;
            size_t r8 = ((size_t)b * L_ + row + 8) * E_ + col;
            *(__half2*)(g_Ahi + r0) = __halves2half2(
                __float2half_rn(acc[mt][nt][0] * x0),
                __float2half_rn(acc[mt][nt][1] * x0));
            *(__half2*)(g_Ahi + r8) = __halves2half2(
                __float2half_rn(acc[mt][nt][2] * x1),
                __float2half_rn(acc[mt][nt][3] * x1));
        }
    }
}

// ---------------- launch ----------------
extern "C" void kernel_launch(void* const* d_in, const int* in_sizes, int n_in,
                              void* d_out, int out_size)
{
    (void)in_sizes; (void)n_in; (void)out_size;
    const float* x  = (const float*)d_in[0];
    const float* z  = (const float*)d_in[1];
    const float* Wq = (const float*)d_in[2];
    const float* bq = (const float*)d_in[3];
    const float* Wk = (const float*)d_in[4];
    const float* bk = (const float*)d_in[5];
    const float* Wv = (const float*)d_in[6];
    const float* bv = (const float*)d_in[7];
    const float* W1 = (const float*)d_in[8];
    const float* b1 = (const float*)d_in[9];
    const float* W2 = (const float*)d_in[10];
    const float* b2 = (const float*)d_in[11];
    float* out = (float*)d_out;

    __half *pAhi, *pBhi, *pQKVhi, *pEhi;
    float *pDen, *pBiasP;
    cudaGetSymbolAddress((void**)&pAhi, g_Ahi);
    cudaGetSymbolAddress((void**)&pBhi, g_Bthi);
    cudaGetSymbolAddress((void**)&pQKVhi, g_QKVhi);
    cudaGetSymbolAddress((void**)&pEhi, g_Ehi);
    cudaGetSymbolAddress((void**)&pDen, g_den);
    cudaGetSymbolAddress((void**)&pBiasP, g_biasP);

    cudaFuncSetAttribute(gemm_mma<0>, cudaFuncAttributeMaxDynamicSharedMemorySize, G_SMEM);
    cudaFuncSetAttribute(gemm_mma<1>, cudaFuncAttributeMaxDynamicSharedMemorySize, G_SMEM);
    cudaFuncSetAttribute(gemm_mma<2>, cudaFuncAttributeMaxDynamicSharedMemorySize, G_SMEM);
    cudaFuncSetAttribute(attn_mma, cudaFuncAttributeMaxDynamicSharedMemorySize, AT_SMEM);

    const size_t nZ = (size_t)ML_ * E_;

    // init: packed bias (bk pre-scaled), out = b2, den = 0
    init_kernel<<<256, 256>>>(bq, bk, bv, b2, out);

    // convert z -> fp16 hi
    convert_hi<<<nZ / 1024, 256>>>(z, pAhi);

    // pack transposed QKV weights (fused 64x64 tiles; Wk pre-scaled by log2e/8)
    transpose_qkv<<<dim3(E_ / 64, E_ / 64, 3), 256>>>(Wq, Wk, Wv, pBhi);

    // fused QKV projection -> fp16 [ML][3072]  (1-term, hi out)
    gemm_mma<0><<<dim3(QKV_LD / 128, ML_ / 128), 256, G_SMEM>>>(
        pAhi, pBhi, pBiasP, nullptr, pQKVhi, nullptr,
        E_, E_, QKV_LD, E_);

    // QK: E = exp2(K'_j . Q_i) fp16 + atomic denom  (1-term)
    gemm_mma<1><<<dim3(L_ / 128, L_ / 128, BH_), 256, G_SMEM>>>(
        pQKVhi, pQKVhi, nullptr, x, pEhi, pDen,
        QKV_LD, QKV_LD, L_, DH_);

    // U = x_j * V / den, fp16
    u_kernel<<<(BH_ * L_ * DH_) / 256, 256>>>(x);

    // attention output -> O fp16 (hi only, into g_Ahi)  (1-term)
    attn_mma<<<dim3(L_ / 128, BH_), 256, AT_SMEM>>>(x);

    // W1 transpose (64x64 tiles, hi only)
    transpose64<<<dim3(HID_ / 64, E_ / 64), 256>>>(W1, pBhi, E_, HID_);

    // MLP1 + fused W2 reduction -> out (atomic, 1-term)
    gemm_mma<2><<<dim3(HID_ / 128, ML_ / 128), 256, G_SMEM>>>(
        pAhi, pBhi, b1, W2, nullptr, out,
        E_, E_, 0, E_);
}